// round 10
// baseline (speedup 1.0000x reference)
#include <cuda_runtime.h>

#define CM_B    64
#define CM_T    256
#define CM_NI   512
#define CM_NO   512
#define CM_NOBS 128
#define ROWS_PER_WARP   2
#define WARPS_PER_BLOCK 4
#define THREADS (WARPS_PER_BLOCK * 32)
#define X_ROW_U2 (CM_NI / 4)   // 128 ulonglong2 per 512-float row
#define FULLM 0xffffffffu

typedef unsigned long long u64;

__device__ __forceinline__ u64 pk2(float lo, float hi) {
    u64 r; asm("mov.b64 %0, {%1, %2};" : "=l"(r) : "f"(lo), "f"(hi)); return r;
}
__device__ __forceinline__ float2 upk2(u64 v) {
    float2 f; asm("mov.b64 {%0, %1}, %2;" : "=f"(f.x), "=f"(f.y) : "l"(v)); return f;
}
__device__ __forceinline__ u64 ffma2(u64 a, u64 b, u64 c) {
    u64 d; asm("fma.rn.f32x2 %0, %1, %2, %3;" : "=l"(d) : "l"(a), "l"(b), "l"(c)); return d;
}
__device__ __forceinline__ u64 fmul2(u64 a, u64 b) {
    u64 d; asm("mul.rn.f32x2 %0, %1, %2;" : "=l"(d) : "l"(a), "l"(b)); return d;
}
__device__ __forceinline__ u64 fadd2(u64 a, u64 b) {
    u64 d; asm("add.rn.f32x2 %0, %1, %2;" : "=l"(d) : "l"(a), "l"(b)); return d;
}
// Integer warp-wide sum; result broadcast to all lanes (f32 redux not on sm_103).
__device__ __forceinline__ int redux_add_s32(int v) {
    int r; asm("redux.sync.add.s32 %0, %1, 0xffffffff;" : "=r"(r) : "r"(v));
    return r;
}
__device__ __forceinline__ float sigmoidf_fast(float v) {
    return __fdividef(1.0f, 1.0f + __expf(-v));
}

#define FXP_SCALE   4194304.0f        // 2^22
#define FXP_INV     (1.0f / 4194304.0f)

// One warp = 2 contiguous observed slots of one batch.
// Lane l owns float4-chunks {k*32 + l, k=0..3} of each 512-float vector (regs).
// REDUX gives all lanes both row sums -> every lane computes BOTH sigmoids
// locally; zero shuffles anywhere in the loop.
__global__ __launch_bounds__(THREADS, 6)
void circuit_kernel(const float* __restrict__ X,
                    const float* __restrict__ Wi,
                    const int*   __restrict__ obs,
                    float*       __restrict__ out) {
    const int b    = blockIdx.x;
    const int warp = threadIdx.x >> 5;
    const int lane = threadIdx.x & 31;
    const int wg   = blockIdx.y * WARPS_PER_BLOCK + warp;  // 0..63
    const int j0   = wg * ROWS_PER_WARP;

    const int  g       = lane >> 4;             // row group 0..1
    const bool sel1    = (g == 1);
    const bool st_pred = (lane & 15) == 0;      // lanes 0,16 store rows 0,1

    // ---- load W rows (coalesced lane layout) ----
    u64 w[ROWS_PER_WARP][8];
    #pragma unroll
    for (int r = 0; r < ROWS_PER_WARP; ++r) {
        const int o = __ldg(&obs[j0 + r]);
        const ulonglong2* wp =
            (const ulonglong2*)(Wi + ((size_t)b * CM_NO + o) * CM_NI) + lane;
        #pragma unroll
        for (int k = 0; k < 4; ++k) {
            ulonglong2 v = __ldg(wp + k * 32);
            w[r][2 * k]     = v.x;
            w[r][2 * k + 1] = v.y;
        }
    }

    const ulonglong2* xb = (const ulonglong2*)(X + (size_t)b * CM_T * CM_NI) + lane;
    float* opl = out + (size_t)b * CM_T * CM_NOBS + j0 + g;   // used iff st_pred

    // preload x_0
    u64 xA[8], xB[8];
    #pragma unroll
    for (int k = 0; k < 4; ++k) {
        ulonglong2 v = __ldg(xb + k * 32);
        xA[2 * k] = v.x; xA[2 * k + 1] = v.y;
    }
    const ulonglong2* pf = xb + X_ROW_U2;

    auto step = [&](const u64* __restrict__ cur, u64* __restrict__ nxt, bool pre) {
        if (pre) {
            #pragma unroll
            for (int k = 0; k < 4; ++k) {
                ulonglong2 v = __ldg(pf + k * 32);
                nxt[2 * k] = v.x; nxt[2 * k + 1] = v.y;
            }
        }
        pf += X_ROW_U2;

        // 2 dot products, 2 packed chains each -> per-lane partials
        float D[ROWS_PER_WARP];
        #pragma unroll
        for (int r = 0; r < ROWS_PER_WARP; ++r) {
            u64 a0 = fmul2(w[r][0], cur[0]);
            u64 a1 = fmul2(w[r][1], cur[1]);
            #pragma unroll
            for (int k = 2; k < 8; k += 2) {
                a0 = ffma2(w[r][k],     cur[k],     a0);
                a1 = ffma2(w[r][k + 1], cur[k + 1], a1);
            }
            float2 s = upk2(fadd2(a0, a1));
            D[r] = s.x + s.y;
        }

        // fixed-point warp reductions: every lane receives both row sums
        int p0 = redux_add_s32(__float2int_rn(D[0] * FXP_SCALE));
        int p1 = redux_add_s32(__float2int_rn(D[1] * FXP_SCALE));

        // both sigmoids computed locally on every lane -> no broadcasts
        const float y0 = sigmoidf_fast(__int2float_rn(p0) * FXP_INV);
        const float y1 = sigmoidf_fast(__int2float_rn(p1) * FXP_INV);

        if (st_pred) *opl = sel1 ? y1 : y0;
        opl += CM_NOBS;

        // rank-1 updates with local constants
        const u64 c0 = pk2(0.01f * y0, 0.01f * y0);
        const u64 c1 = pk2(0.01f * y1, 0.01f * y1);
        #pragma unroll
        for (int k = 0; k < 8; ++k) {
            w[0][k] = ffma2(c0, cur[k], w[0][k]);
            w[1][k] = ffma2(c1, cur[k], w[1][k]);
        }
    };

    #pragma unroll 1
    for (int t = 0; t < CM_T; t += 2) {
        step(xA, xB, true);              // t:   compute, prefetch t+1
        step(xB, xA, t + 2 < CM_T);      // t+1: compute, prefetch t+2
    }
}

extern "C" void kernel_launch(void* const* d_in, const int* in_sizes, int n_in,
                              void* d_out, int out_size) {
    const float* X   = (const float*)d_in[0];
    const float* Wi  = (const float*)d_in[1];
    const int*   obs = (const int*)d_in[2];
    float*       out = (float*)d_out;

    dim3 grid(CM_B, CM_NOBS / (ROWS_PER_WARP * WARPS_PER_BLOCK));  // 64 x 16
    circuit_kernel<<<grid, THREADS>>>(X, Wi, obs, out);
}